// round 1
// baseline (speedup 1.0000x reference)
#include <cuda_runtime.h>
#include <cstdint>
#include <math.h>

// Problem constants
#define E_ 8
#define C_ 1024
#define H_ 2048
#define I_ 5632

// Scratch: inter/gate buffer [E, C, I] fp32 (176 MB). Static device array — no allocs.
__device__ float g_scratch[(size_t)E_ * C_ * I_];

// ---------------- tile config ----------------
constexpr int BM = 128, BN = 128, BK = 32;
constexpr int PAD = 4;
constexpr int LDS_ = BK + PAD;           // 36 floats per smem row
constexpr int THREADS = 256;
constexpr size_t SMEM_BYTES = (size_t)2 * (BM * LDS_ + BN * LDS_) * sizeof(float); // 73728

// ---------------- PTX helpers ----------------
__device__ __forceinline__ uint32_t f2tf32(float x) {
    uint32_t y;
    asm("cvt.rna.tf32.f32 %0, %1;" : "=r"(y) : "f"(x));
    return y;
}

__device__ __forceinline__ void mma_tf32(float (&c)[4], const uint32_t (&a)[4],
                                         const uint32_t (&b)[2]) {
    asm volatile(
        "mma.sync.aligned.m16n8k8.row.col.f32.tf32.tf32.f32 "
        "{%0,%1,%2,%3}, {%4,%5,%6,%7}, {%8,%9}, {%0,%1,%2,%3};\n"
        : "+f"(c[0]), "+f"(c[1]), "+f"(c[2]), "+f"(c[3])
        : "r"(a[0]), "r"(a[1]), "r"(a[2]), "r"(a[3]), "r"(b[0]), "r"(b[1]));
}

__device__ __forceinline__ void cp_async16(void* smem_ptr, const void* gmem_ptr) {
    uint32_t s = (uint32_t)__cvta_generic_to_shared(smem_ptr);
    asm volatile("cp.async.cg.shared.global [%0], [%1], 16;\n" ::"r"(s), "l"(gmem_ptr));
}
__device__ __forceinline__ void cp_commit() { asm volatile("cp.async.commit_group;\n"); }
template <int N>
__device__ __forceinline__ void cp_wait() {
    asm volatile("cp.async.wait_group %0;\n" ::"n"(N));
}

// ---------------- GEMM kernel ----------------
// C[e, m, n] = sum_k A[e, m, k] * B[e, n, k]   (NT gemm, both operands K-contiguous)
// MODE 0: store raw accumulator           (gate GEMM -> scratch)
// MODE 1: out = silu(Gpre[idx]) * acc     (up GEMM, fused SwiGLU, in-place into scratch)
// MODE 2: store raw accumulator           (down GEMM -> d_out)
template <int MODE>
__global__ void __launch_bounds__(THREADS)
gemm_nt(const float* __restrict__ A, const float* __restrict__ B,
        const float* __restrict__ Gpre, float* __restrict__ Cout,
        int M, int N, int K,
        long strideA, long strideB, long strideC) {
    extern __shared__ float smem[];
    float* As = smem;                        // [2][BM][LDS_]
    float* Bs = smem + 2 * BM * LDS_;        // [2][BN][LDS_]

    const int e = blockIdx.z;
    const float* Ae = A + (long)e * strideA;
    const float* Be = B + (long)e * strideB;

    const int bm = blockIdx.y, bn = blockIdx.x;
    const int tid = threadIdx.x;
    const int warp = tid >> 5, lane = tid & 31;
    const int wm = warp >> 1, wn = warp & 1;      // 4 warps in M, 2 in N
    const int gid = lane >> 2, tig = lane & 3;    // mma fragment coords

    // global->smem load assignment: 16B per thread per row-chunk
    const int lrow = tid >> 3;          // 0..31
    const int lcol = (tid & 7) * 4;     // float offset within BK

    const float* Ag = Ae + (long)(bm * BM + lrow) * K + lcol;
    const float* Bg = Be + (long)(bn * BN + lrow) * K + lcol;

    float acc[2][8][4];
#pragma unroll
    for (int mt = 0; mt < 2; mt++)
#pragma unroll
        for (int nt = 0; nt < 8; nt++)
#pragma unroll
            for (int r = 0; r < 4; r++) acc[mt][nt][r] = 0.f;

    const int KT = K / BK;

    // prologue: stage 0
    {
        float* as = As;
        float* bs = Bs;
#pragma unroll
        for (int i = 0; i < 4; i++) {
            cp_async16(&as[(lrow + i * 32) * LDS_ + lcol], Ag + (long)(i * 32) * K);
            cp_async16(&bs[(lrow + i * 32) * LDS_ + lcol], Bg + (long)(i * 32) * K);
        }
        cp_commit();
    }

    for (int kt = 0; kt < KT; ++kt) {
        if (kt + 1 < KT) {
            const long koff = (long)(kt + 1) * BK;
            float* as = As + ((kt + 1) & 1) * BM * LDS_;
            float* bs = Bs + ((kt + 1) & 1) * BN * LDS_;
#pragma unroll
            for (int i = 0; i < 4; i++) {
                cp_async16(&as[(lrow + i * 32) * LDS_ + lcol], Ag + (long)(i * 32) * K + koff);
                cp_async16(&bs[(lrow + i * 32) * LDS_ + lcol], Bg + (long)(i * 32) * K + koff);
            }
        }
        cp_commit();
        cp_wait<1>();
        __syncthreads();

        const float* as = As + (kt & 1) * BM * LDS_;
        const float* bs = Bs + (kt & 1) * BN * LDS_;

#pragma unroll
        for (int k8 = 0; k8 < BK / 8; k8++) {
            const int kc = k8 * 8;
            uint32_t afr[2][4];
            uint32_t bfr[8][2];
#pragma unroll
            for (int mt = 0; mt < 2; mt++) {
                const int r = wm * 32 + mt * 16 + gid;
                afr[mt][0] = f2tf32(as[r * LDS_ + kc + tig]);
                afr[mt][1] = f2tf32(as[(r + 8) * LDS_ + kc + tig]);
                afr[mt][2] = f2tf32(as[r * LDS_ + kc + tig + 4]);
                afr[mt][3] = f2tf32(as[(r + 8) * LDS_ + kc + tig + 4]);
            }
#pragma unroll
            for (int nt = 0; nt < 8; nt++) {
                const int c = wn * 64 + nt * 8 + gid;
                bfr[nt][0] = f2tf32(bs[c * LDS_ + kc + tig]);
                bfr[nt][1] = f2tf32(bs[c * LDS_ + kc + tig + 4]);
            }
#pragma unroll
            for (int mt = 0; mt < 2; mt++)
#pragma unroll
                for (int nt = 0; nt < 8; nt++) mma_tf32(acc[mt][nt], afr[mt], bfr[nt]);
        }
        __syncthreads();
    }

    // ---------------- epilogue ----------------
    const long base = (long)e * strideC;
#pragma unroll
    for (int mt = 0; mt < 2; mt++) {
#pragma unroll
        for (int nt = 0; nt < 8; nt++) {
            const int row0 = bm * BM + wm * 32 + mt * 16 + gid;
            const int col = bn * BN + wn * 64 + nt * 8 + tig * 2;
            const long i0 = base + (long)row0 * N + col;
            const long i1 = base + (long)(row0 + 8) * N + col;
            float2 v01 = make_float2(acc[mt][nt][0], acc[mt][nt][1]);
            float2 v23 = make_float2(acc[mt][nt][2], acc[mt][nt][3]);
            if (MODE == 1) {
                const float2 g0 = *reinterpret_cast<const float2*>(Gpre + i0);
                const float2 g1 = *reinterpret_cast<const float2*>(Gpre + i1);
                v01.x *= g0.x / (1.f + __expf(-g0.x));
                v01.y *= g0.y / (1.f + __expf(-g0.y));
                v23.x *= g1.x / (1.f + __expf(-g1.x));
                v23.y *= g1.y / (1.f + __expf(-g1.y));
            }
            *reinterpret_cast<float2*>(Cout + i0) = v01;
            *reinterpret_cast<float2*>(Cout + i1) = v23;
        }
    }
}

// ---------------- host launcher ----------------
extern "C" void kernel_launch(void* const* d_in, const int* in_sizes, int n_in,
                              void* d_out, int out_size) {
    const float* x    = (const float*)d_in[0];  // [E, C, H]
    const float* gate = (const float*)d_in[1];  // [E, I, H]
    const float* up   = (const float*)d_in[2];  // [E, I, H]
    const float* down = (const float*)d_in[3];  // [E, H, I]
    float* out = (float*)d_out;                 // [E, C, H]

    float* scratch = nullptr;
    cudaGetSymbolAddress((void**)&scratch, g_scratch);

    cudaFuncSetAttribute(gemm_nt<0>, cudaFuncAttributeMaxDynamicSharedMemorySize, SMEM_BYTES);
    cudaFuncSetAttribute(gemm_nt<1>, cudaFuncAttributeMaxDynamicSharedMemorySize, SMEM_BYTES);
    cudaFuncSetAttribute(gemm_nt<2>, cudaFuncAttributeMaxDynamicSharedMemorySize, SMEM_BYTES);

    dim3 blk(THREADS);

    // 1) gate = X · Gateᵀ  -> scratch  [E, C, I]
    gemm_nt<0><<<dim3(I_ / BN, C_ / BM, E_), blk, SMEM_BYTES>>>(
        x, gate, nullptr, scratch,
        C_, I_, H_,
        (long)C_ * H_, (long)I_ * H_, (long)C_ * I_);

    // 2) inter = silu(gate) * (X · Upᵀ)  -> scratch (in place)
    gemm_nt<1><<<dim3(I_ / BN, C_ / BM, E_), blk, SMEM_BYTES>>>(
        x, up, scratch, scratch,
        C_, I_, H_,
        (long)C_ * H_, (long)I_ * H_, (long)C_ * I_);

    // 3) out = inter · Downᵀ  [E, C, H]
    gemm_nt<2><<<dim3(H_ / BN, C_ / BM, E_), blk, SMEM_BYTES>>>(
        scratch, down, nullptr, out,
        C_, H_, I_,
        (long)C_ * I_, (long)H_ * I_, (long)C_ * H_);
}

// round 2
// speedup vs baseline: 1.0031x; 1.0031x over previous
#include <cuda_runtime.h>
#include <cstdint>
#include <math.h>

// Problem constants
#define E_ 8
#define C_ 1024
#define H_ 2048
#define I_ 5632

// Scratch: inter/gate buffer [E, C, I] fp32 (176 MB). Static device array — no allocs.
__device__ float g_scratch[(size_t)E_ * C_ * I_];

// ---------------- tile config ----------------
constexpr int BM = 128, BN = 128, BK = 32;
constexpr int PAD = 4;
constexpr int LDS_ = BK + PAD;           // 36 floats per smem row
constexpr int THREADS = 256;
constexpr size_t SMEM_BYTES = (size_t)2 * (BM * LDS_ + BN * LDS_) * sizeof(float); // 73728

// ---------------- PTX helpers ----------------
__device__ __forceinline__ uint32_t f2tf32(float x) {
    uint32_t y;
    asm("cvt.rna.tf32.f32 %0, %1;" : "=r"(y) : "f"(x));
    return y;
}

__device__ __forceinline__ void mma_tf32(float (&c)[4], const uint32_t (&a)[4],
                                         const uint32_t (&b)[2]) {
    asm volatile(
        "mma.sync.aligned.m16n8k8.row.col.f32.tf32.tf32.f32 "
        "{%0,%1,%2,%3}, {%4,%5,%6,%7}, {%8,%9}, {%0,%1,%2,%3};\n"
        : "+f"(c[0]), "+f"(c[1]), "+f"(c[2]), "+f"(c[3])
        : "r"(a[0]), "r"(a[1]), "r"(a[2]), "r"(a[3]), "r"(b[0]), "r"(b[1]));
}

__device__ __forceinline__ void cp_async16(void* smem_ptr, const void* gmem_ptr) {
    uint32_t s = (uint32_t)__cvta_generic_to_shared(smem_ptr);
    asm volatile("cp.async.cg.shared.global [%0], [%1], 16;\n" ::"r"(s), "l"(gmem_ptr));
}
__device__ __forceinline__ void cp_commit() { asm volatile("cp.async.commit_group;\n"); }
template <int N>
__device__ __forceinline__ void cp_wait() {
    asm volatile("cp.async.wait_group %0;\n" ::"n"(N));
}

// ---------------- GEMM kernel ----------------
// C[e, m, n] = sum_k A[e, m, k] * B[e, n, k]   (NT gemm, both operands K-contiguous)
// MODE 0: store raw accumulator           (gate GEMM -> scratch)
// MODE 1: out = silu(Gpre[idx]) * acc     (up GEMM, fused SwiGLU, in-place into scratch)
// MODE 2: store raw accumulator           (down GEMM -> d_out)
template <int MODE>
__global__ void __launch_bounds__(THREADS)
gemm_nt(const float* __restrict__ A, const float* __restrict__ B,
        const float* __restrict__ Gpre, float* __restrict__ Cout,
        int M, int N, int K,
        long strideA, long strideB, long strideC) {
    extern __shared__ float smem[];
    float* As = smem;                        // [2][BM][LDS_]
    float* Bs = smem + 2 * BM * LDS_;        // [2][BN][LDS_]

    const int e = blockIdx.z;
    const float* Ae = A + (long)e * strideA;
    const float* Be = B + (long)e * strideB;

    const int bm = blockIdx.y, bn = blockIdx.x;
    const int tid = threadIdx.x;
    const int warp = tid >> 5, lane = tid & 31;
    const int wm = warp >> 1, wn = warp & 1;      // 4 warps in M, 2 in N
    const int gid = lane >> 2, tig = lane & 3;    // mma fragment coords

    // global->smem load assignment: 16B per thread per row-chunk
    const int lrow = tid >> 3;          // 0..31
    const int lcol = (tid & 7) * 4;     // float offset within BK

    const float* Ag = Ae + (long)(bm * BM + lrow) * K + lcol;
    const float* Bg = Be + (long)(bn * BN + lrow) * K + lcol;

    float acc[2][8][4];
#pragma unroll
    for (int mt = 0; mt < 2; mt++)
#pragma unroll
        for (int nt = 0; nt < 8; nt++)
#pragma unroll
            for (int r = 0; r < 4; r++) acc[mt][nt][r] = 0.f;

    const int KT = K / BK;

    // prologue: stage 0
    {
        float* as = As;
        float* bs = Bs;
#pragma unroll
        for (int i = 0; i < 4; i++) {
            cp_async16(&as[(lrow + i * 32) * LDS_ + lcol], Ag + (long)(i * 32) * K);
            cp_async16(&bs[(lrow + i * 32) * LDS_ + lcol], Bg + (long)(i * 32) * K);
        }
        cp_commit();
    }

    for (int kt = 0; kt < KT; ++kt) {
        if (kt + 1 < KT) {
            const long koff = (long)(kt + 1) * BK;
            float* as = As + ((kt + 1) & 1) * BM * LDS_;
            float* bs = Bs + ((kt + 1) & 1) * BN * LDS_;
#pragma unroll
            for (int i = 0; i < 4; i++) {
                cp_async16(&as[(lrow + i * 32) * LDS_ + lcol], Ag + (long)(i * 32) * K + koff);
                cp_async16(&bs[(lrow + i * 32) * LDS_ + lcol], Bg + (long)(i * 32) * K + koff);
            }
        }
        cp_commit();
        cp_wait<1>();
        __syncthreads();

        const float* as = As + (kt & 1) * BM * LDS_;
        const float* bs = Bs + (kt & 1) * BN * LDS_;

#pragma unroll
        for (int k8 = 0; k8 < BK / 8; k8++) {
            const int kc = k8 * 8;
            uint32_t afr[2][4];
            uint32_t bfr[8][2];
#pragma unroll
            for (int mt = 0; mt < 2; mt++) {
                const int r = wm * 32 + mt * 16 + gid;
                afr[mt][0] = f2tf32(as[r * LDS_ + kc + tig]);
                afr[mt][1] = f2tf32(as[(r + 8) * LDS_ + kc + tig]);
                afr[mt][2] = f2tf32(as[r * LDS_ + kc + tig + 4]);
                afr[mt][3] = f2tf32(as[(r + 8) * LDS_ + kc + tig + 4]);
            }
#pragma unroll
            for (int nt = 0; nt < 8; nt++) {
                const int c = wn * 64 + nt * 8 + gid;
                bfr[nt][0] = f2tf32(bs[c * LDS_ + kc + tig]);
                bfr[nt][1] = f2tf32(bs[c * LDS_ + kc + tig + 4]);
            }
#pragma unroll
            for (int mt = 0; mt < 2; mt++)
#pragma unroll
                for (int nt = 0; nt < 8; nt++) mma_tf32(acc[mt][nt], afr[mt], bfr[nt]);
        }
        __syncthreads();
    }

    // ---------------- epilogue ----------------
    const long base = (long)e * strideC;
#pragma unroll
    for (int mt = 0; mt < 2; mt++) {
#pragma unroll
        for (int nt = 0; nt < 8; nt++) {
            const int row0 = bm * BM + wm * 32 + mt * 16 + gid;
            const int col = bn * BN + wn * 64 + nt * 8 + tig * 2;
            const long i0 = base + (long)row0 * N + col;
            const long i1 = base + (long)(row0 + 8) * N + col;
            float2 v01 = make_float2(acc[mt][nt][0], acc[mt][nt][1]);
            float2 v23 = make_float2(acc[mt][nt][2], acc[mt][nt][3]);
            if (MODE == 1) {
                const float2 g0 = *reinterpret_cast<const float2*>(Gpre + i0);
                const float2 g1 = *reinterpret_cast<const float2*>(Gpre + i1);
                v01.x *= g0.x / (1.f + __expf(-g0.x));
                v01.y *= g0.y / (1.f + __expf(-g0.y));
                v23.x *= g1.x / (1.f + __expf(-g1.x));
                v23.y *= g1.y / (1.f + __expf(-g1.y));
            }
            *reinterpret_cast<float2*>(Cout + i0) = v01;
            *reinterpret_cast<float2*>(Cout + i1) = v23;
        }
    }
}

// ---------------- host launcher ----------------
extern "C" void kernel_launch(void* const* d_in, const int* in_sizes, int n_in,
                              void* d_out, int out_size) {
    const float* x    = (const float*)d_in[0];  // [E, C, H]
    const float* gate = (const float*)d_in[1];  // [E, I, H]
    const float* up   = (const float*)d_in[2];  // [E, I, H]
    const float* down = (const float*)d_in[3];  // [E, H, I]
    float* out = (float*)d_out;                 // [E, C, H]

    float* scratch = nullptr;
    cudaGetSymbolAddress((void**)&scratch, g_scratch);

    cudaFuncSetAttribute(gemm_nt<0>, cudaFuncAttributeMaxDynamicSharedMemorySize, SMEM_BYTES);
    cudaFuncSetAttribute(gemm_nt<1>, cudaFuncAttributeMaxDynamicSharedMemorySize, SMEM_BYTES);
    cudaFuncSetAttribute(gemm_nt<2>, cudaFuncAttributeMaxDynamicSharedMemorySize, SMEM_BYTES);

    dim3 blk(THREADS);

    // 1) gate = X · Gateᵀ  -> scratch  [E, C, I]
    gemm_nt<0><<<dim3(I_ / BN, C_ / BM, E_), blk, SMEM_BYTES>>>(
        x, gate, nullptr, scratch,
        C_, I_, H_,
        (long)C_ * H_, (long)I_ * H_, (long)C_ * I_);

    // 2) inter = silu(gate) * (X · Upᵀ)  -> scratch (in place)
    gemm_nt<1><<<dim3(I_ / BN, C_ / BM, E_), blk, SMEM_BYTES>>>(
        x, up, scratch, scratch,
        C_, I_, H_,
        (long)C_ * H_, (long)I_ * H_, (long)C_ * I_);

    // 3) out = inter · Downᵀ  [E, C, H]
    gemm_nt<2><<<dim3(H_ / BN, C_ / BM, E_), blk, SMEM_BYTES>>>(
        scratch, down, nullptr, out,
        C_, H_, I_,
        (long)C_ * I_, (long)H_ * I_, (long)C_ * H_);
}